// round 13
// baseline (speedup 1.0000x reference)
#include <cuda_runtime.h>
#include <math.h>

#define LAYERS 2
#define BB 8
#define TT 512
#define HH 128
#define MM (BB*TT)   // 4096 rows

// ---------------- device scratch ----------------
__device__ float  g_Wt[LAYERS][6][HH*HH];  // transposed weights [l][p][d][h]
__device__ float  g_q[MM*HH];              // q
__device__ float  g_k[MM*HH];              // k / sqrt(H)
__device__ float  g_i[MM*HH];              // exp(i)   (planar, for den warp)
__device__ float  g_f[MM*HH];              // sigm(f)  (planar, for den warp)
__device__ float4 g_gates[MM*HH];          // packed (i, f, v, o) per (m, h)
__device__ float  g_h[MM*HH];              // UNNORMALIZED hidden (o * C.q)
__device__ float  g_rden[MM];              // 1 / max(|n.q|, 1) per (b,t)

// ---------------- weight transpose ----------------
__global__ void transpose_w_kernel(const float* __restrict__ Wq, const float* __restrict__ Wk,
                                   const float* __restrict__ Wv, const float* __restrict__ Wi,
                                   const float* __restrict__ Wf, const float* __restrict__ Wo)
{
    int idx = blockIdx.x * blockDim.x + threadIdx.x;
    const int total = LAYERS * 6 * HH * HH;
    if (idx >= total) return;
    int l   = idx / (6 * HH * HH);
    int rem = idx - l * 6 * HH * HH;
    int p   = rem / (HH * HH);
    int e   = rem - p * (HH * HH);
    int d   = e >> 7;
    int h   = e & 127;
    const float* W = (p == 0) ? Wq : (p == 1) ? Wk : (p == 2) ? Wv
                   : (p == 3) ? Wi : (p == 4) ? Wf : Wo;
    g_Wt[l][p][d * HH + h] = W[l * HH * HH + h * HH + d];
}

// ---------------- projection GEMM + bias + activation (round-6 exact) ----------------
// 64x128 tile, BK=8, 128 threads, 8x8 microtile. grid (MM/64, 6) = 384 CTAs.
// For layer 1 (X==nullptr) the A operand is g_h scaled by g_rden (fused norm).
__global__ __launch_bounds__(128) void proj_gemm_kernel(
    const float* __restrict__ X, int layer,
    const float* __restrict__ bq, const float* __restrict__ bk,
    const float* __restrict__ bv, const float* __restrict__ bi,
    const float* __restrict__ bf, const float* __restrict__ bo)
{
    const float* __restrict__ Xp = X ? X : g_h;
    const int p  = blockIdx.y;
    const int m0 = blockIdx.x * 64;
    const float* __restrict__ Wt = g_Wt[layer][p];

    __shared__ float As[8][64];
    __shared__ float Bs[8][128];

    const int tid = threadIdx.x;
    const int tx = tid & 15;          // 16 col groups (x8 = 128)
    const int ty = tid >> 4;          // 8 row groups  (x8 = 64)
    const int lm = tid >> 1;          // 0..63 : M row for X load
    const int lk = (tid & 1) << 2;    // 0 or 4
    const int wh = (tid & 15) << 3;   // 0..120
    const int wk = tid >> 4;          // 0..7

    const float rd = X ? 1.0f : g_rden[m0 + lm];  // fused normalization of layer-0 output

    float acc[8][8];
    #pragma unroll
    for (int i = 0; i < 8; i++)
        #pragma unroll
        for (int j = 0; j < 8; j++) acc[i][j] = 0.0f;

    for (int k0 = 0; k0 < HH; k0 += 8) {
        float4 xa = *(const float4*)(Xp + (m0 + lm) * HH + k0 + lk);
        float4 wa = *(const float4*)(Wt + (k0 + wk) * HH + wh);
        float4 wb = *(const float4*)(Wt + (k0 + wk) * HH + wh + 4);
        As[lk + 0][lm] = xa.x * rd;
        As[lk + 1][lm] = xa.y * rd;
        As[lk + 2][lm] = xa.z * rd;
        As[lk + 3][lm] = xa.w * rd;
        *(float4*)(&Bs[wk][wh])     = wa;
        *(float4*)(&Bs[wk][wh + 4]) = wb;
        __syncthreads();
        #pragma unroll
        for (int kk = 0; kk < 8; kk++) {
            float a[8], b[8];
            *(float4*)(a)     = *(const float4*)(&As[kk][ty * 8]);
            *(float4*)(a + 4) = *(const float4*)(&As[kk][ty * 8 + 4]);
            *(float4*)(b)     = *(const float4*)(&Bs[kk][tx * 8]);
            *(float4*)(b + 4) = *(const float4*)(&Bs[kk][tx * 8 + 4]);
            #pragma unroll
            for (int i = 0; i < 8; i++)
                #pragma unroll
                for (int j = 0; j < 8; j++)
                    acc[i][j] = fmaf(a[i], b[j], acc[i][j]);
        }
        __syncthreads();
    }

    const float* __restrict__ bias =
        (p == 0) ? bq : (p == 1) ? bk : (p == 2) ? bv
      : (p == 3) ? bi : (p == 4) ? bf : bo;
    const float kscale = 0.088388347648318447f;  // 1/sqrt(128)

    #pragma unroll
    for (int i = 0; i < 8; i++) {
        const int m = m0 + ty * 8 + i;
        #pragma unroll
        for (int j = 0; j < 8; j++) {
            const int h = tx * 8 + j;
            float v = acc[i][j] + bias[layer * HH + h];
            const int e = m * HH + h;
            if (p == 0) {
                g_q[e] = v;
            } else if (p == 1) {
                g_k[e] = v * kscale;
            } else if (p == 2) {
                g_gates[e].z = v;                       // v
            } else if (p == 3) {
                v = expf(v);
                g_i[e] = v; g_gates[e].x = v;           // i
            } else if (p == 4) {
                v = 1.0f / (1.0f + expf(-v));
                g_f[e] = v; g_gates[e].y = v;           // f
            } else {
                v = 1.0f / (1.0f + expf(-v));
                g_gates[e].w = v;                       // o
            }
        }
    }
}

// Merge-tree reduction of 8 per-lane values over 32 lanes: 9 SHFL total.
// (used by the denominator warp only)
__device__ __forceinline__ float reduce8_merge(const float dp[8], int lane)
{
    const bool h4 = (lane & 16) != 0;
    float x0, x1, x2, x3;
    {
        float a, b;
        a = h4 ? dp[4] : dp[0]; b = h4 ? dp[0] : dp[4];
        x0 = a + __shfl_xor_sync(0xffffffffu, b, 16);
        a = h4 ? dp[5] : dp[1]; b = h4 ? dp[1] : dp[5];
        x1 = a + __shfl_xor_sync(0xffffffffu, b, 16);
        a = h4 ? dp[6] : dp[2]; b = h4 ? dp[2] : dp[6];
        x2 = a + __shfl_xor_sync(0xffffffffu, b, 16);
        a = h4 ? dp[7] : dp[3]; b = h4 ? dp[3] : dp[7];
        x3 = a + __shfl_xor_sync(0xffffffffu, b, 16);
    }
    const bool h3 = (lane & 8) != 0;
    float z0, z1;
    {
        float a, b;
        a = h3 ? x2 : x0; b = h3 ? x0 : x2;
        z0 = a + __shfl_xor_sync(0xffffffffu, b, 8);
        a = h3 ? x3 : x1; b = h3 ? x1 : x3;
        z1 = a + __shfl_xor_sync(0xffffffffu, b, 8);
    }
    const bool h2 = (lane & 4) != 0;
    float w;
    {
        float a = h2 ? z1 : z0, b = h2 ? z0 : z1;
        w = a + __shfl_xor_sync(0xffffffffu, b, 4);
    }
    w += __shfl_xor_sync(0xffffffffu, w, 2);
    w += __shfl_xor_sync(0xffffffffu, w, 1);
    return w;
}

// ---------------- column-partitioned mLSTM scan ----------------
// grid (17, 8), block 256 (8 warps).   <-- 256 THREADS: the design needs 8 warps
//  bx < 16 : CTA owns rows r0 = bx*8 .. r0+7 of batch b. Warp w owns COLUMNS
//            [16w, 16w+16) of all 8 rows; lane (rl = lane>>2, cg = lane&3)
//            holds C[rl][16w + 4cg .. +3]. Per warp-step loads: q-slice float4
//            (1 wavefront, broadcast over rl), k-slice (1), gates for 8 rows =
//            one 128B line (1). Per-step intra-warp reduction = 2 SHFLs (cg
//            quad); cross-warp reduction deferred to once per 8-step group via
//            double-buffered smem + ONE __syncthreads per group.
//  bx == 16: warp 0 runs the denominator recurrence (unchanged).
__global__ __launch_bounds__(256) void scan_kernel()
{
    const int b    = blockIdx.y;
    const int w    = threadIdx.x >> 5;   // 0..7 with 256 threads
    const int lane = threadIdx.x & 31;

    if (blockIdx.x == 16) {
        // ---- denominator warp ----
        if (w != 0) return;
        const int c4   = lane << 2;
        const int sidx = (lane >> 2) & 7;
        const bool wl  = (lane & 3) == 0;
        const float* __restrict__ Pq = g_q + b * TT * HH + c4;
        const float* __restrict__ Pk = g_k + b * TT * HH + c4;
        const float* __restrict__ Pi = g_i + b * TT * HH + c4;
        const float* __restrict__ Pf = g_f + b * TT * HH + c4;
        float* __restrict__ Dr = g_rden + b * TT;

        float4 qb[8], kb[8], ib[8], fb[8];
        #pragma unroll
        for (int s = 0; s < 8; s++) {
            qb[s] = *(const float4*)(Pq + s * HH);
            kb[s] = *(const float4*)(Pk + s * HH);
            ib[s] = *(const float4*)(Pi + s * HH);
            fb[s] = *(const float4*)(Pf + s * HH);
        }
        float n0 = 0.f, n1 = 0.f, n2 = 0.f, n3 = 0.f;

        for (int gI = 0; gI < 64; gI++) {
            float pd[8];
            #pragma unroll
            for (int s = 0; s < 8; s++) {
                float4 q = qb[s], k = kb[s], ii = ib[s], ff = fb[s];
                pd[s] = n0 * q.x + n1 * q.y + n2 * q.z + n3 * q.w;  // uses OLD n
                n0 = fmaf(ff.x, n0, ii.x * k.x);
                n1 = fmaf(ff.y, n1, ii.y * k.y);
                n2 = fmaf(ff.z, n2, ii.z * k.z);
                n3 = fmaf(ff.w, n3, ii.w * k.w);
                if (gI < 63) {
                    const int off = (gI * 8 + s + 8) * HH;
                    qb[s] = *(const float4*)(Pq + off);
                    kb[s] = *(const float4*)(Pk + off);
                    ib[s] = *(const float4*)(Pi + off);
                    fb[s] = *(const float4*)(Pf + off);
                }
            }
            const float tot = reduce8_merge(pd, lane);
            if (wl) Dr[gI * 8 + sidx] = 1.0f / fmaxf(fabsf(tot), 1.0f);
        }
        return;
    }

    // ---- column-partitioned row CTA ----
    const int cg  = lane & 3;         // column sub-group within warp
    const int rl  = lane >> 2;        // local row 0..7
    const int r0  = blockIdx.x * 8;   // CTA's row base
    const int col = w * 16 + cg * 4;  // this lane's first column

    const float*  __restrict__ Pq = g_q + b * TT * HH + col;
    const float*  __restrict__ Pk = g_k + b * TT * HH + col;
    const float4* __restrict__ Pg = g_gates + b * TT * HH + r0 + rl;
    float* __restrict__ Dst = g_h + b * TT * HH + r0;

    // partial scoreboard: [buf][step][row][warp] (pad 9 -> conflict-free)
    __shared__ float part[2][8][8][9];

    float4 qb[8], kb[8], gb[8];
    #pragma unroll
    for (int s = 0; s < 8; s++) {
        qb[s] = *(const float4*)(Pq + s * HH);
        kb[s] = *(const float4*)(Pk + s * HH);
        gb[s] = Pg[s * HH];
    }
    float C0 = 0.f, C1 = 0.f, C2 = 0.f, C3 = 0.f;

    for (int gI = 0; gI < 64; gI++) {
        const int buf = gI & 1;
        float dp[8];
        #pragma unroll
        for (int s = 0; s < 8; s++) {
            float4 q = qb[s], k = kb[s], gg = gb[s];   // gg = (i,f,v,o)[r0+rl]
            // partial h_tilde for row rl over this lane's 4 cols, pre-scaled by o
            dp[s] = gg.w * (C0 * q.x + C1 * q.y + C2 * q.z + C3 * q.w);
            const float aa = gg.x * gg.z;              // i * v
            C0 = fmaf(gg.y, C0, aa * k.x);
            C1 = fmaf(gg.y, C1, aa * k.y);
            C2 = fmaf(gg.y, C2, aa * k.z);
            C3 = fmaf(gg.y, C3, aa * k.w);
            if (gI < 63) {
                const int off = (gI * 8 + s + 8) * HH;
                qb[s] = *(const float4*)(Pq + off);
                kb[s] = *(const float4*)(Pk + off);
                gb[s] = Pg[off];
            }
        }
        // intra-warp: sum over the 4 cg lanes of each row quad (2 SHFLs/step)
        #pragma unroll
        for (int s = 0; s < 8; s++) {
            dp[s] += __shfl_xor_sync(0xffffffffu, dp[s], 1);
            dp[s] += __shfl_xor_sync(0xffffffffu, dp[s], 2);
        }
        if (cg == 0) {
            #pragma unroll
            for (int s = 0; s < 8; s++)
                part[buf][s][rl][w] = dp[s];
        }
        __syncthreads();
        // cross-warp: warp w reduces step s = w; lane rl < 8 handles row rl
        if (lane < 8) {
            float sum = 0.f;
            #pragma unroll
            for (int j = 0; j < 8; j++) sum += part[buf][w][lane][j];
            Dst[(gI * 8 + w) * HH + lane] = sum;       // unnormalized
        }
    }
}

// ---------------- final normalization ----------------
__global__ void normalize_kernel(float* __restrict__ out)
{
    const int idx = blockIdx.x * 256 + threadIdx.x;
    out[idx] = g_h[idx] * g_rden[idx >> 7];
}

// ---------------- launcher ----------------
extern "C" void kernel_launch(void* const* d_in, const int* in_sizes, int n_in,
                              void* d_out, int out_size)
{
    const float* x  = (const float*)d_in[0];
    const float* Wq = (const float*)d_in[1];
    const float* Wk = (const float*)d_in[2];
    const float* Wv = (const float*)d_in[3];
    const float* Wi = (const float*)d_in[4];
    const float* Wf = (const float*)d_in[5];
    const float* Wo = (const float*)d_in[6];
    const float* bq = (const float*)d_in[7];
    const float* bk = (const float*)d_in[8];
    const float* bv = (const float*)d_in[9];
    const float* bi = (const float*)d_in[10];
    const float* bf = (const float*)d_in[11];
    const float* bo = (const float*)d_in[12];
    float* out = (float*)d_out;

    const int total_w = LAYERS * 6 * HH * HH;
    transpose_w_kernel<<<(total_w + 255) / 256, 256>>>(Wq, Wk, Wv, Wi, Wf, Wo);

    dim3 ggrid(MM / 64, 6);
    dim3 sgrid(17, BB);

    // layer 0
    proj_gemm_kernel<<<ggrid, 128>>>(x, 0, bq, bk, bv, bi, bf, bo);
    scan_kernel<<<sgrid, 256>>>();                        // g_h (raw) + g_rden
    // layer 1 (normalization of layer-0 output fused into A-load)
    proj_gemm_kernel<<<ggrid, 128>>>(nullptr, 1, bq, bk, bv, bi, bf, bo);
    scan_kernel<<<sgrid, 256>>>();                        // g_h (raw) + g_rden
    // final normalize into d_out
    normalize_kernel<<<(MM * HH) / 256, 256>>>(out);
}

// round 16
// speedup vs baseline: 1.2442x; 1.2442x over previous
#include <cuda_runtime.h>
#include <cuda_bf16.h>
#include <math.h>
#include <stdint.h>

#define LAYERS 2
#define BB 8
#define TT 512
#define HH 128
#define MM (BB*TT)   // 4096 rows

// ---------------- device scratch ----------------
__device__ __nv_bfloat16 g_Wh[LAYERS][6][HH*HH];  // weight hi bf16, [l][p][h][d]
__device__ __nv_bfloat16 g_Wl[LAYERS][6][HH*HH];  // weight lo bf16
__device__ float  g_q[MM*HH];              // q
__device__ float  g_k[MM*HH];              // k / sqrt(H)
__device__ float  g_i[MM*HH];              // exp(i)   (planar, for den warp)
__device__ float  g_f[MM*HH];              // sigm(f)  (planar, for den warp)
__device__ float4 g_gates[MM*HH];          // packed (i, f, v, o) per (m, h)
__device__ float  g_h[MM*HH];              // UNNORMALIZED hidden (o * C.q)
__device__ float  g_rden[MM];              // 1 / max(|n.q|, 1) per (b,t)

__device__ __forceinline__ uint32_t smem_to_u32(const void* p) {
    uint32_t a;
    asm("{ .reg .u64 t; cvta.to.shared.u64 t, %1; cvt.u32.u64 %0, t; }" : "=r"(a) : "l"(p));
    return a;
}
__device__ __forceinline__ uint32_t pk_bf16(__nv_bfloat16 a, __nv_bfloat16 b) {
    return (uint32_t)__bfloat16_as_ushort(a) | ((uint32_t)__bfloat16_as_ushort(b) << 16);
}

// ---------------- weight split: fp32 -> bf16 hi/lo (once) ----------------
__global__ void prep_w_kernel(const float* __restrict__ Wq, const float* __restrict__ Wk,
                              const float* __restrict__ Wv, const float* __restrict__ Wi,
                              const float* __restrict__ Wf, const float* __restrict__ Wo)
{
    int idx = blockIdx.x * blockDim.x + threadIdx.x;
    const int total = LAYERS * 6 * HH * HH;
    if (idx >= total) return;
    int l   = idx / (6 * HH * HH);
    int rem = idx - l * 6 * HH * HH;
    int p   = rem / (HH * HH);
    int e   = rem - p * (HH * HH);
    const float* W = (p == 0) ? Wq : (p == 1) ? Wk : (p == 2) ? Wv
                   : (p == 3) ? Wi : (p == 4) ? Wf : Wo;
    float wv = W[l * HH * HH + e];
    __nv_bfloat16 hi = __float2bfloat16(wv);
    __nv_bfloat16 lo = __float2bfloat16(wv - __bfloat162float(hi));
    g_Wh[l][p][e] = hi;
    g_Wl[l][p][e] = lo;
}

// ---------------- tensor-core projection via mma.sync (sm_80 ISA) ----------------
// OUT[t, h] = act( sum_d X[t,d] * W[h,d] + bias[h] ), fp32 via bf16x3:
//   D = Wh·Xh + Wh·Xl + Wl·Xh   (fp32 accumulate in MMA)
// CTA: 64 tokens x 128 heads, one projection p = blockIdx.y. 128 threads (4 warps),
// warp quadrant 32t x 64h. K processed in 2 chunks of 64. SMEM tiles padded to
// 72 bf16 (144B) rows -> ldmatrix 8-row fetches hit 8 distinct 16B bank groups.
#define KC   64            // k-chunk
#define PAD  72            // padded row length in bf16
#define SM_XH 0
#define SM_XL (64 * PAD * 2)
#define SM_WH (2 * 64 * PAD * 2)
#define SM_WL (SM_WH + HH * PAD * 2)
#define SMEM_TOTAL_MMA (SM_WL + HH * PAD * 2)   // 55296 B

__device__ __forceinline__ void mma16816(float c[4], const uint32_t a[4], const uint32_t b[2]) {
    asm volatile(
        "mma.sync.aligned.m16n8k16.row.col.f32.bf16.bf16.f32 "
        "{%0,%1,%2,%3}, {%4,%5,%6,%7}, {%8,%9}, {%0,%1,%2,%3};"
        : "+f"(c[0]), "+f"(c[1]), "+f"(c[2]), "+f"(c[3])
        : "r"(a[0]), "r"(a[1]), "r"(a[2]), "r"(a[3]), "r"(b[0]), "r"(b[1]));
}
__device__ __forceinline__ void ldsm4(uint32_t r[4], uint32_t addr) {
    asm volatile("ldmatrix.sync.aligned.m8n8.x4.shared.b16 {%0,%1,%2,%3}, [%4];"
                 : "=r"(r[0]), "=r"(r[1]), "=r"(r[2]), "=r"(r[3]) : "r"(addr));
}

__global__ __launch_bounds__(128) void mma_proj_kernel(
    const float* __restrict__ X, int layer,
    const float* __restrict__ bq, const float* __restrict__ bk,
    const float* __restrict__ bv, const float* __restrict__ bi,
    const float* __restrict__ bf, const float* __restrict__ bo)
{
    extern __shared__ char smem[];
    const uint32_t sb = smem_to_u32(smem);
    const float* __restrict__ Xp = X ? X : g_h;
    const int p    = blockIdx.y;
    const int t0   = blockIdx.x * 64;
    const int tid  = threadIdx.x;
    const int lane = tid & 31;
    const int w    = tid >> 5;
    const int m_base = (w & 1) * 32;      // warp token base (within CTA)
    const int n_base = (w >> 1) * 64;     // warp head base

    const __nv_bfloat16* __restrict__ WhG = &g_Wh[layer][p][0];
    const __nv_bfloat16* __restrict__ WlG = &g_Wl[layer][p][0];

    float acc[2][8][4];
    #pragma unroll
    for (int i = 0; i < 2; i++)
        #pragma unroll
        for (int j = 0; j < 8; j++)
            #pragma unroll
            for (int r = 0; r < 4; r++) acc[i][j][r] = 0.0f;

    // ldmatrix per-lane address components (matrix j = lane>>3, row = lane&7)
    const int a_row = ((lane >> 3) & 1) * 8 + (lane & 7);  // + m_base + mt*16
    const int a_col = (lane >> 4) * 8;                     // + ks*16
    const int b_row = (lane >> 4) * 8 + (lane & 7);        // + n_base + np*16
    const int b_col = ((lane >> 3) & 1) * 8;               // + ks*16

    for (int kc = 0; kc < 2; kc++) {
        const int k0 = kc * KC;
        // ---- convert X chunk: 64 tokens x 64 d -> Xh, Xl ----
        for (int i = tid; i < 1024; i += 128) {
            const int row = i >> 4;
            const int c4  = (i & 15) << 2;
            float4 xv = *(const float4*)(Xp + (t0 + row) * HH + k0 + c4);
            if (!X) {
                const float rd = g_rden[t0 + row];
                xv.x *= rd; xv.y *= rd; xv.z *= rd; xv.w *= rd;
            }
            __nv_bfloat16 h0 = __float2bfloat16(xv.x), h1 = __float2bfloat16(xv.y);
            __nv_bfloat16 h2 = __float2bfloat16(xv.z), h3 = __float2bfloat16(xv.w);
            __nv_bfloat16 l0 = __float2bfloat16(xv.x - __bfloat162float(h0));
            __nv_bfloat16 l1 = __float2bfloat16(xv.y - __bfloat162float(h1));
            __nv_bfloat16 l2 = __float2bfloat16(xv.z - __bfloat162float(h2));
            __nv_bfloat16 l3 = __float2bfloat16(xv.w - __bfloat162float(h3));
            const int off = row * (PAD * 2) + c4 * 2;
            *(uint2*)(smem + SM_XH + off) = make_uint2(pk_bf16(h0, h1), pk_bf16(h2, h3));
            *(uint2*)(smem + SM_XL + off) = make_uint2(pk_bf16(l0, l1), pk_bf16(l2, l3));
        }
        // ---- copy W chunk: 128 heads x 64 d (bf16, contiguous 128B per row) ----
        {
            const int h = tid;  // one row per thread
            const uint4* sh = (const uint4*)(WhG + h * HH + k0);
            const uint4* sl = (const uint4*)(WlG + h * HH + k0);
            uint4* dh = (uint4*)(smem + SM_WH + h * (PAD * 2));
            uint4* dl = (uint4*)(smem + SM_WL + h * (PAD * 2));
            #pragma unroll
            for (int j = 0; j < 8; j++) { dh[j] = sh[j]; dl[j] = sl[j]; }
        }
        __syncthreads();

        // ---- 3 passes x 4 k-steps of K=16 ----
        #pragma unroll
        for (int pass = 0; pass < 3; pass++) {
            const uint32_t At = sb + (pass == 1 ? SM_XL : SM_XH);
            const uint32_t Bt = sb + (pass == 2 ? SM_WL : SM_WH);
            #pragma unroll
            for (int ks = 0; ks < 4; ks++) {
                uint32_t a[2][4];
                #pragma unroll
                for (int mt = 0; mt < 2; mt++) {
                    const int row = m_base + mt * 16 + a_row;
                    const int col = ks * 16 + a_col;
                    ldsm4(a[mt], At + row * (PAD * 2) + col * 2);
                }
                uint32_t b[8][2];
                #pragma unroll
                for (int np = 0; np < 4; np++) {
                    const int n = n_base + np * 16 + b_row;
                    const int k = ks * 16 + b_col;
                    uint32_t r[4];
                    ldsm4(r, Bt + n * (PAD * 2) + k * 2);
                    b[np * 2][0] = r[0]; b[np * 2][1] = r[1];
                    b[np * 2 + 1][0] = r[2]; b[np * 2 + 1][1] = r[3];
                }
                #pragma unroll
                for (int mt = 0; mt < 2; mt++)
                    #pragma unroll
                    for (int nt = 0; nt < 8; nt++)
                        mma16816(acc[mt][nt], a[mt], b[nt]);
            }
        }
        __syncthreads();
    }

    // ---- epilogue: bias + activation + scatter ----
    const float* __restrict__ bias =
        (p == 0) ? bq : (p == 1) ? bk : (p == 2) ? bv
      : (p == 3) ? bi : (p == 4) ? bf : bo;
    const float kscale = 0.088388347648318447f;  // 1/sqrt(128)
    const int gid = lane >> 2, tig = lane & 3;

    #pragma unroll
    for (int mt = 0; mt < 2; mt++) {
        const int tr = t0 + m_base + mt * 16 + gid;
        #pragma unroll
        for (int nt = 0; nt < 8; nt++) {
            const int h0 = n_base + nt * 8 + 2 * tig;
            #pragma unroll
            for (int r = 0; r < 4; r++) {
                const int tok = tr + (r >> 1) * 8;
                const int h   = h0 + (r & 1);
                float v = acc[mt][nt][r] + bias[layer * HH + h];
                const int e = tok * HH + h;
                if (p == 0) {
                    g_q[e] = v;
                } else if (p == 1) {
                    g_k[e] = v * kscale;
                } else if (p == 2) {
                    g_gates[e].z = v;                       // v
                } else if (p == 3) {
                    v = expf(v);
                    g_i[e] = v; g_gates[e].x = v;           // i
                } else if (p == 4) {
                    v = 1.0f / (1.0f + expf(-v));
                    g_f[e] = v; g_gates[e].y = v;           // f
                } else {
                    v = 1.0f / (1.0f + expf(-v));
                    g_gates[e].w = v;                       // o
                }
            }
        }
    }
}

// Merge-tree reduction of 8 per-lane values over 32 lanes: 9 SHFL total.
__device__ __forceinline__ float reduce8_merge(const float dp[8], int lane)
{
    const bool h4 = (lane & 16) != 0;
    float x0, x1, x2, x3;
    {
        float a, b;
        a = h4 ? dp[4] : dp[0]; b = h4 ? dp[0] : dp[4];
        x0 = a + __shfl_xor_sync(0xffffffffu, b, 16);
        a = h4 ? dp[5] : dp[1]; b = h4 ? dp[1] : dp[5];
        x1 = a + __shfl_xor_sync(0xffffffffu, b, 16);
        a = h4 ? dp[6] : dp[2]; b = h4 ? dp[2] : dp[6];
        x2 = a + __shfl_xor_sync(0xffffffffu, b, 16);
        a = h4 ? dp[7] : dp[3]; b = h4 ? dp[3] : dp[7];
        x3 = a + __shfl_xor_sync(0xffffffffu, b, 16);
    }
    const bool h3 = (lane & 8) != 0;
    float z0, z1;
    {
        float a, b;
        a = h3 ? x2 : x0; b = h3 ? x0 : x2;
        z0 = a + __shfl_xor_sync(0xffffffffu, b, 8);
        a = h3 ? x3 : x1; b = h3 ? x1 : x3;
        z1 = a + __shfl_xor_sync(0xffffffffu, b, 8);
    }
    const bool h2 = (lane & 4) != 0;
    float w;
    {
        float a = h2 ? z1 : z0, b = h2 ? z0 : z1;
        w = a + __shfl_xor_sync(0xffffffffu, b, 4);
    }
    w += __shfl_xor_sync(0xffffffffu, w, 2);
    w += __shfl_xor_sync(0xffffffffu, w, 1);
    return w;
}

// ---------------- barrier-free mLSTM scan (round-10 exact) ----------------
__global__ __launch_bounds__(256) void scan_kernel()
{
    const int b    = blockIdx.y;
    const int w    = threadIdx.x >> 5;
    const int lane = threadIdx.x & 31;
    const int c4   = lane << 2;
    const int sidx = (lane >> 2) & 7;
    const bool wl  = (lane & 3) == 0;

    if (blockIdx.x == 16) {
        if (w != 0) return;
        const float* __restrict__ Pq = g_q + b * TT * HH + c4;
        const float* __restrict__ Pk = g_k + b * TT * HH + c4;
        const float* __restrict__ Pi = g_i + b * TT * HH + c4;
        const float* __restrict__ Pf = g_f + b * TT * HH + c4;
        float* __restrict__ Dr = g_rden + b * TT;

        float4 qb[8], kb[8], ib[8], fb[8];
        #pragma unroll
        for (int s = 0; s < 8; s++) {
            qb[s] = *(const float4*)(Pq + s * HH);
            kb[s] = *(const float4*)(Pk + s * HH);
            ib[s] = *(const float4*)(Pi + s * HH);
            fb[s] = *(const float4*)(Pf + s * HH);
        }
        float n0 = 0.f, n1 = 0.f, n2 = 0.f, n3 = 0.f;

        for (int gI = 0; gI < 64; gI++) {
            float pd[8];
            #pragma unroll
            for (int s = 0; s < 8; s++) {
                float4 q = qb[s], k = kb[s], ii = ib[s], ff = fb[s];
                pd[s] = n0 * q.x + n1 * q.y + n2 * q.z + n3 * q.w;  // OLD n
                n0 = fmaf(ff.x, n0, ii.x * k.x);
                n1 = fmaf(ff.y, n1, ii.y * k.y);
                n2 = fmaf(ff.z, n2, ii.z * k.z);
                n3 = fmaf(ff.w, n3, ii.w * k.w);
                if (gI < 63) {
                    const int off = (gI * 8 + s + 8) * HH;
                    qb[s] = *(const float4*)(Pq + off);
                    kb[s] = *(const float4*)(Pk + off);
                    ib[s] = *(const float4*)(Pi + off);
                    fb[s] = *(const float4*)(Pf + off);
                }
            }
            const float tot = reduce8_merge(pd, lane);
            if (wl) Dr[gI * 8 + sidx] = 1.0f / fmaxf(fabsf(tot), 1.0f);
        }
        return;
    }

    const int r = blockIdx.x * 8 + w;
    const float*  __restrict__ Pq = g_q + b * TT * HH + c4;
    const float*  __restrict__ Pk = g_k + b * TT * HH + c4;
    const float4* __restrict__ Pg = g_gates + b * TT * HH + r;
    float* __restrict__ Dst = g_h + b * TT * HH + r;

    float4 qb[8], kb[8], gb[8];
    #pragma unroll
    for (int s = 0; s < 8; s++) {
        qb[s] = *(const float4*)(Pq + s * HH);
        kb[s] = *(const float4*)(Pk + s * HH);
        gb[s] = Pg[s * HH];
    }
    float C0 = 0.f, C1 = 0.f, C2 = 0.f, C3 = 0.f;

    for (int gI = 0; gI < 64; gI++) {
        float dp[8];
        #pragma unroll
        for (int s = 0; s < 8; s++) {
            float4 q = qb[s], k = kb[s], gg = gb[s];   // (i, f, v, o)[r]
            dp[s] = gg.w * (C0 * q.x + C1 * q.y + C2 * q.z + C3 * q.w);
            const float aa = gg.x * gg.z;
            C0 = fmaf(gg.y, C0, aa * k.x);
            C1 = fmaf(gg.y, C1, aa * k.y);
            C2 = fmaf(gg.y, C2, aa * k.z);
            C3 = fmaf(gg.y, C3, aa * k.w);
            if (gI < 63) {
                const int off = (gI * 8 + s + 8) * HH;
                qb[s] = *(const float4*)(Pq + off);
                kb[s] = *(const float4*)(Pk + off);
                gb[s] = Pg[off];
            }
        }
        const float tot = reduce8_merge(dp, lane);
        if (wl) Dst[(gI * 8 + sidx) * HH] = tot;       // unnormalized
    }
}

// ---------------- final normalization ----------------
__global__ void normalize_kernel(float* __restrict__ out)
{
    const int idx = blockIdx.x * 256 + threadIdx.x;
    out[idx] = g_h[idx] * g_rden[idx >> 7];
}

// ---------------- launcher ----------------
extern "C" void kernel_launch(void* const* d_in, const int* in_sizes, int n_in,
                              void* d_out, int out_size)
{
    const float* x  = (const float*)d_in[0];
    const float* Wq = (const float*)d_in[1];
    const float* Wk = (const float*)d_in[2];
    const float* Wv = (const float*)d_in[3];
    const float* Wi = (const float*)d_in[4];
    const float* Wf = (const float*)d_in[5];
    const float* Wo = (const float*)d_in[6];
    const float* bq = (const float*)d_in[7];
    const float* bk = (const float*)d_in[8];
    const float* bv = (const float*)d_in[9];
    const float* bi = (const float*)d_in[10];
    const float* bf = (const float*)d_in[11];
    const float* bo = (const float*)d_in[12];
    float* out = (float*)d_out;

    cudaFuncSetAttribute(mma_proj_kernel,
                         cudaFuncAttributeMaxDynamicSharedMemorySize, SMEM_TOTAL_MMA);

    const int total_w = LAYERS * 6 * HH * HH;
    prep_w_kernel<<<(total_w + 255) / 256, 256>>>(Wq, Wk, Wv, Wi, Wf, Wo);

    dim3 ggrid(MM / 64, 6);
    dim3 sgrid(17, BB);

    // layer 0
    mma_proj_kernel<<<ggrid, 128, SMEM_TOTAL_MMA>>>(x, 0, bq, bk, bv, bi, bf, bo);
    scan_kernel<<<sgrid, 256>>>();                        // g_h (raw) + g_rden
    // layer 1 (normalization of layer-0 output fused into X conversion)
    mma_proj_kernel<<<ggrid, 128, SMEM_TOTAL_MMA>>>(nullptr, 1, bq, bk, bv, bi, bf, bo);
    scan_kernel<<<sgrid, 256>>>();                        // g_h (raw) + g_rden
    // final normalize into d_out
    normalize_kernel<<<(MM * HH) / 256, 256>>>(out);
}

// round 17
// speedup vs baseline: 1.3882x; 1.1157x over previous
#include <cuda_runtime.h>
#include <cuda_bf16.h>
#include <math.h>
#include <stdint.h>

#define LAYERS 2
#define BB 8
#define TT 512
#define HH 128
#define MM (BB*TT)   // 4096 rows

// ---------------- device scratch ----------------
__device__ __nv_bfloat16 g_Wh[LAYERS][6][HH*HH];  // weight hi bf16, [l][p][h][d]
__device__ __nv_bfloat16 g_Wl[LAYERS][6][HH*HH];  // weight lo bf16
__device__ __nv_bfloat16 g_Xh[MM*HH];      // activation hi bf16 (per layer)
__device__ __nv_bfloat16 g_Xl[MM*HH];      // activation lo bf16
__device__ float  g_q[MM*HH];              // q
__device__ float  g_k[MM*HH];              // k / sqrt(H)
__device__ float  g_i[MM*HH];              // exp(i)   (planar, for den warp)
__device__ float  g_f[MM*HH];              // sigm(f)  (planar, for den warp)
__device__ float4 g_gates[MM*HH];          // packed (i, f, v, o) per (m, h)
__device__ float  g_h[MM*HH];              // UNNORMALIZED hidden (o * C.q)
__device__ float  g_rden[MM];              // 1 / max(|n.q|, 1) per (b,t)

__device__ __forceinline__ uint32_t smem_to_u32(const void* p) {
    uint32_t a;
    asm("{ .reg .u64 t; cvta.to.shared.u64 t, %1; cvt.u32.u64 %0, t; }" : "=r"(a) : "l"(p));
    return a;
}
__device__ __forceinline__ uint32_t pk_bf16(__nv_bfloat16 a, __nv_bfloat16 b) {
    return (uint32_t)__bfloat16_as_ushort(a) | ((uint32_t)__bfloat16_as_ushort(b) << 16);
}

// ---------------- weight split: fp32 -> bf16 hi/lo (once) ----------------
__global__ void prep_w_kernel(const float* __restrict__ Wq, const float* __restrict__ Wk,
                              const float* __restrict__ Wv, const float* __restrict__ Wi,
                              const float* __restrict__ Wf, const float* __restrict__ Wo)
{
    int idx = blockIdx.x * blockDim.x + threadIdx.x;
    const int total = LAYERS * 6 * HH * HH;
    if (idx >= total) return;
    int l   = idx / (6 * HH * HH);
    int rem = idx - l * 6 * HH * HH;
    int p   = rem / (HH * HH);
    int e   = rem - p * (HH * HH);
    const float* W = (p == 0) ? Wq : (p == 1) ? Wk : (p == 2) ? Wv
                   : (p == 3) ? Wi : (p == 4) ? Wf : Wo;
    float wv = W[l * HH * HH + e];
    __nv_bfloat16 hi = __float2bfloat16(wv);
    __nv_bfloat16 lo = __float2bfloat16(wv - __bfloat162float(hi));
    g_Wh[l][p][e] = hi;
    g_Wl[l][p][e] = lo;
}

// ---------------- activation split: fp32 -> bf16 hi/lo (once per layer) ----
// X == nullptr: source is g_h scaled by g_rden (layer-1 fused normalization).
__global__ void prep_x_kernel(const float* __restrict__ X)
{
    const int i4 = blockIdx.x * 256 + threadIdx.x;   // float4 index
    const float* __restrict__ src = X ? X : g_h;
    float4 xv = *(const float4*)(src + (size_t)i4 * 4);
    if (!X) {
        const float rd = g_rden[(i4 * 4) >> 7];
        xv.x *= rd; xv.y *= rd; xv.z *= rd; xv.w *= rd;
    }
    __nv_bfloat16 h0 = __float2bfloat16(xv.x), h1 = __float2bfloat16(xv.y);
    __nv_bfloat16 h2 = __float2bfloat16(xv.z), h3 = __float2bfloat16(xv.w);
    __nv_bfloat16 l0 = __float2bfloat16(xv.x - __bfloat162float(h0));
    __nv_bfloat16 l1 = __float2bfloat16(xv.y - __bfloat162float(h1));
    __nv_bfloat16 l2 = __float2bfloat16(xv.z - __bfloat162float(h2));
    __nv_bfloat16 l3 = __float2bfloat16(xv.w - __bfloat162float(h3));
    ((uint2*)g_Xh)[i4] = make_uint2(pk_bf16(h0, h1), pk_bf16(h2, h3));
    ((uint2*)g_Xl)[i4] = make_uint2(pk_bf16(l0, l1), pk_bf16(l2, l3));
}

// ---------------- tensor-core projection via mma.sync ----------------
// OUT[t, h] = act( sum_d X[t,d] * W[h,d] + bias[h] ), bf16x3 fp32-emulation.
// CTA: 64 tokens x 128 heads, one projection. 256 threads (8 warps), warp tile
// 32t x 32h -> acc = 32 regs/thread. K in 2 chunks of 64. Rows padded to 72
// bf16 (144B) so ldmatrix 8-row fetches hit 8 distinct 16B bank groups.
// Fragments (a_h, a_l, b_h, b_l) loaded ONCE per k-step, reused for 3 passes.
#define KC   64
#define PAD  72
#define SM_XH 0
#define SM_XL (64 * PAD * 2)
#define SM_WH (2 * 64 * PAD * 2)
#define SM_WL (SM_WH + HH * PAD * 2)
#define SMEM_TOTAL_MMA (SM_WL + HH * PAD * 2)   // 55296 B

__device__ __forceinline__ void mma16816(float c[4], const uint32_t a[4], const uint32_t b[2]) {
    asm volatile(
        "mma.sync.aligned.m16n8k16.row.col.f32.bf16.bf16.f32 "
        "{%0,%1,%2,%3}, {%4,%5,%6,%7}, {%8,%9}, {%0,%1,%2,%3};"
        : "+f"(c[0]), "+f"(c[1]), "+f"(c[2]), "+f"(c[3])
        : "r"(a[0]), "r"(a[1]), "r"(a[2]), "r"(a[3]), "r"(b[0]), "r"(b[1]));
}
__device__ __forceinline__ void ldsm4(uint32_t r[4], uint32_t addr) {
    asm volatile("ldmatrix.sync.aligned.m8n8.x4.shared.b16 {%0,%1,%2,%3}, [%4];"
                 : "=r"(r[0]), "=r"(r[1]), "=r"(r[2]), "=r"(r[3]) : "r"(addr));
}

__global__ __launch_bounds__(256, 2) void mma_proj_kernel(
    int layer,
    const float* __restrict__ bq, const float* __restrict__ bk,
    const float* __restrict__ bv, const float* __restrict__ bi,
    const float* __restrict__ bf, const float* __restrict__ bo)
{
    extern __shared__ char smem[];
    const uint32_t sb = smem_to_u32(smem);
    const int p    = blockIdx.y;
    const int t0   = blockIdx.x * 64;
    const int tid  = threadIdx.x;
    const int lane = tid & 31;
    const int w    = tid >> 5;
    const int m_base = (w & 1) * 32;      // warp token base (within CTA)
    const int n_base = (w >> 1) * 32;     // warp head base (4 groups x 32 = 128)

    const char* __restrict__ WhG = (const char*)&g_Wh[layer][p][0];
    const char* __restrict__ WlG = (const char*)&g_Wl[layer][p][0];
    const char* __restrict__ XhG = (const char*)g_Xh;
    const char* __restrict__ XlG = (const char*)g_Xl;

    float acc[2][4][4];
    #pragma unroll
    for (int i = 0; i < 2; i++)
        #pragma unroll
        for (int j = 0; j < 4; j++)
            #pragma unroll
            for (int r = 0; r < 4; r++) acc[i][j][r] = 0.0f;

    // ldmatrix per-lane address components
    const int a_row = ((lane >> 3) & 1) * 8 + (lane & 7);
    const int a_col = (lane >> 4) * 8;
    const int b_row = (lane >> 4) * 8 + (lane & 7);
    const int b_col = ((lane >> 3) & 1) * 8;

    for (int kc = 0; kc < 2; kc++) {
        const int k0 = kc * KC;
        // ---- stage X chunk (bf16 copy): 64 rows x 128B, both tensors ----
        for (int i = tid; i < 512; i += 256) {
            const int row = i >> 3, j = i & 7;
            const int so = (t0 + row) * 256 + k0 * 2 + j * 16;
            const int dofs = row * (PAD * 2) + j * 16;
            *(uint4*)(smem + SM_XH + dofs) = *(const uint4*)(XhG + so);
            *(uint4*)(smem + SM_XL + dofs) = *(const uint4*)(XlG + so);
        }
        // ---- stage W chunk: 128 rows x 128B, both tensors ----
        for (int i = tid; i < 1024; i += 256) {
            const int row = i >> 3, j = i & 7;
            const int so = row * 256 + k0 * 2 + j * 16;
            const int dofs = row * (PAD * 2) + j * 16;
            *(uint4*)(smem + SM_WH + dofs) = *(const uint4*)(WhG + so);
            *(uint4*)(smem + SM_WL + dofs) = *(const uint4*)(WlG + so);
        }
        __syncthreads();

        #pragma unroll
        for (int ks = 0; ks < 4; ks++) {
            uint32_t ah[2][4], al[2][4];
            #pragma unroll
            for (int mt = 0; mt < 2; mt++) {
                const uint32_t ao = (uint32_t)(m_base + mt * 16 + a_row) * (PAD * 2)
                                  + (uint32_t)(ks * 16 + a_col) * 2;
                ldsm4(ah[mt], sb + SM_XH + ao);
                ldsm4(al[mt], sb + SM_XL + ao);
            }
            uint32_t bh[4][2], bl[4][2];
            #pragma unroll
            for (int np = 0; np < 2; np++) {
                const uint32_t bo_ = (uint32_t)(n_base + np * 16 + b_row) * (PAD * 2)
                                   + (uint32_t)(ks * 16 + b_col) * 2;
                uint32_t r[4];
                ldsm4(r, sb + SM_WH + bo_);
                bh[np * 2][0] = r[0]; bh[np * 2][1] = r[1];
                bh[np * 2 + 1][0] = r[2]; bh[np * 2 + 1][1] = r[3];
                ldsm4(r, sb + SM_WL + bo_);
                bl[np * 2][0] = r[0]; bl[np * 2][1] = r[1];
                bl[np * 2 + 1][0] = r[2]; bl[np * 2 + 1][1] = r[3];
            }
            #pragma unroll
            for (int mt = 0; mt < 2; mt++)
                #pragma unroll
                for (int nt = 0; nt < 4; nt++) {
                    mma16816(acc[mt][nt], ah[mt], bh[nt]);
                    mma16816(acc[mt][nt], al[mt], bh[nt]);
                    mma16816(acc[mt][nt], ah[mt], bl[nt]);
                }
        }
        __syncthreads();
    }

    // ---- epilogue: bias + activation + scatter ----
    const float* __restrict__ bias =
        (p == 0) ? bq : (p == 1) ? bk : (p == 2) ? bv
      : (p == 3) ? bi : (p == 4) ? bf : bo;
    const float kscale = 0.088388347648318447f;  // 1/sqrt(128)
    const int gid = lane >> 2, tig = lane & 3;

    #pragma unroll
    for (int mt = 0; mt < 2; mt++) {
        const int tr = t0 + m_base + mt * 16 + gid;
        #pragma unroll
        for (int nt = 0; nt < 4; nt++) {
            const int h0 = n_base + nt * 8 + 2 * tig;
            #pragma unroll
            for (int r = 0; r < 4; r++) {
                const int tok = tr + (r >> 1) * 8;
                const int h   = h0 + (r & 1);
                float v = acc[mt][nt][r] + bias[layer * HH + h];
                const int e = tok * HH + h;
                if (p == 0) {
                    g_q[e] = v;
                } else if (p == 1) {
                    g_k[e] = v * kscale;
                } else if (p == 2) {
                    g_gates[e].z = v;                       // v
                } else if (p == 3) {
                    v = expf(v);
                    g_i[e] = v; g_gates[e].x = v;           // i
                } else if (p == 4) {
                    v = 1.0f / (1.0f + expf(-v));
                    g_f[e] = v; g_gates[e].y = v;           // f
                } else {
                    v = 1.0f / (1.0f + expf(-v));
                    g_gates[e].w = v;                       // o
                }
            }
        }
    }
}

// Merge-tree reduction of 8 per-lane values over 32 lanes: 9 SHFL total.
__device__ __forceinline__ float reduce8_merge(const float dp[8], int lane)
{
    const bool h4 = (lane & 16) != 0;
    float x0, x1, x2, x3;
    {
        float a, b;
        a = h4 ? dp[4] : dp[0]; b = h4 ? dp[0] : dp[4];
        x0 = a + __shfl_xor_sync(0xffffffffu, b, 16);
        a = h4 ? dp[5] : dp[1]; b = h4 ? dp[1] : dp[5];
        x1 = a + __shfl_xor_sync(0xffffffffu, b, 16);
        a = h4 ? dp[6] : dp[2]; b = h4 ? dp[2] : dp[6];
        x2 = a + __shfl_xor_sync(0xffffffffu, b, 16);
        a = h4 ? dp[7] : dp[3]; b = h4 ? dp[3] : dp[7];
        x3 = a + __shfl_xor_sync(0xffffffffu, b, 16);
    }
    const bool h3 = (lane & 8) != 0;
    float z0, z1;
    {
        float a, b;
        a = h3 ? x2 : x0; b = h3 ? x0 : x2;
        z0 = a + __shfl_xor_sync(0xffffffffu, b, 8);
        a = h3 ? x3 : x1; b = h3 ? x1 : x3;
        z1 = a + __shfl_xor_sync(0xffffffffu, b, 8);
    }
    const bool h2 = (lane & 4) != 0;
    float w;
    {
        float a = h2 ? z1 : z0, b = h2 ? z0 : z1;
        w = a + __shfl_xor_sync(0xffffffffu, b, 4);
    }
    w += __shfl_xor_sync(0xffffffffu, w, 2);
    w += __shfl_xor_sync(0xffffffffu, w, 1);
    return w;
}

// ---------------- barrier-free mLSTM scan (round-10 exact) ----------------
__global__ __launch_bounds__(256) void scan_kernel()
{
    const int b    = blockIdx.y;
    const int w    = threadIdx.x >> 5;
    const int lane = threadIdx.x & 31;
    const int c4   = lane << 2;
    const int sidx = (lane >> 2) & 7;
    const bool wl  = (lane & 3) == 0;

    if (blockIdx.x == 16) {
        if (w != 0) return;
        const float* __restrict__ Pq = g_q + b * TT * HH + c4;
        const float* __restrict__ Pk = g_k + b * TT * HH + c4;
        const float* __restrict__ Pi = g_i + b * TT * HH + c4;
        const float* __restrict__ Pf = g_f + b * TT * HH + c4;
        float* __restrict__ Dr = g_rden + b * TT;

        float4 qb[8], kb[8], ib[8], fb[8];
        #pragma unroll
        for (int s = 0; s < 8; s++) {
            qb[s] = *(const float4*)(Pq + s * HH);
            kb[s] = *(const float4*)(Pk + s * HH);
            ib[s] = *(const float4*)(Pi + s * HH);
            fb[s] = *(const float4*)(Pf + s * HH);
        }
        float n0 = 0.f, n1 = 0.f, n2 = 0.f, n3 = 0.f;

        for (int gI = 0; gI < 64; gI++) {
            float pd[8];
            #pragma unroll
            for (int s = 0; s < 8; s++) {
                float4 q = qb[s], k = kb[s], ii = ib[s], ff = fb[s];
                pd[s] = n0 * q.x + n1 * q.y + n2 * q.z + n3 * q.w;  // OLD n
                n0 = fmaf(ff.x, n0, ii.x * k.x);
                n1 = fmaf(ff.y, n1, ii.y * k.y);
                n2 = fmaf(ff.z, n2, ii.z * k.z);
                n3 = fmaf(ff.w, n3, ii.w * k.w);
                if (gI < 63) {
                    const int off = (gI * 8 + s + 8) * HH;
                    qb[s] = *(const float4*)(Pq + off);
                    kb[s] = *(const float4*)(Pk + off);
                    ib[s] = *(const float4*)(Pi + off);
                    fb[s] = *(const float4*)(Pf + off);
                }
            }
            const float tot = reduce8_merge(pd, lane);
            if (wl) Dr[gI * 8 + sidx] = 1.0f / fmaxf(fabsf(tot), 1.0f);
        }
        return;
    }

    const int r = blockIdx.x * 8 + w;
    const float*  __restrict__ Pq = g_q + b * TT * HH + c4;
    const float*  __restrict__ Pk = g_k + b * TT * HH + c4;
    const float4* __restrict__ Pg = g_gates + b * TT * HH + r;
    float* __restrict__ Dst = g_h + b * TT * HH + r;

    float4 qb[8], kb[8], gb[8];
    #pragma unroll
    for (int s = 0; s < 8; s++) {
        qb[s] = *(const float4*)(Pq + s * HH);
        kb[s] = *(const float4*)(Pk + s * HH);
        gb[s] = Pg[s * HH];
    }
    float C0 = 0.f, C1 = 0.f, C2 = 0.f, C3 = 0.f;

    for (int gI = 0; gI < 64; gI++) {
        float dp[8];
        #pragma unroll
        for (int s = 0; s < 8; s++) {
            float4 q = qb[s], k = kb[s], gg = gb[s];   // (i, f, v, o)[r]
            dp[s] = gg.w * (C0 * q.x + C1 * q.y + C2 * q.z + C3 * q.w);
            const float aa = gg.x * gg.z;
            C0 = fmaf(gg.y, C0, aa * k.x);
            C1 = fmaf(gg.y, C1, aa * k.y);
            C2 = fmaf(gg.y, C2, aa * k.z);
            C3 = fmaf(gg.y, C3, aa * k.w);
            if (gI < 63) {
                const int off = (gI * 8 + s + 8) * HH;
                qb[s] = *(const float4*)(Pq + off);
                kb[s] = *(const float4*)(Pk + off);
                gb[s] = Pg[off];
            }
        }
        const float tot = reduce8_merge(dp, lane);
        if (wl) Dst[(gI * 8 + sidx) * HH] = tot;       // unnormalized
    }
}

// ---------------- final normalization ----------------
__global__ void normalize_kernel(float* __restrict__ out)
{
    const int idx = blockIdx.x * 256 + threadIdx.x;
    out[idx] = g_h[idx] * g_rden[idx >> 7];
}

// ---------------- launcher ----------------
extern "C" void kernel_launch(void* const* d_in, const int* in_sizes, int n_in,
                              void* d_out, int out_size)
{
    const float* x  = (const float*)d_in[0];
    const float* Wq = (const float*)d_in[1];
    const float* Wk = (const float*)d_in[2];
    const float* Wv = (const float*)d_in[3];
    const float* Wi = (const float*)d_in[4];
    const float* Wf = (const float*)d_in[5];
    const float* Wo = (const float*)d_in[6];
    const float* bq = (const float*)d_in[7];
    const float* bk = (const float*)d_in[8];
    const float* bv = (const float*)d_in[9];
    const float* bi = (const float*)d_in[10];
    const float* bf = (const float*)d_in[11];
    const float* bo = (const float*)d_in[12];
    float* out = (float*)d_out;

    cudaFuncSetAttribute(mma_proj_kernel,
                         cudaFuncAttributeMaxDynamicSharedMemorySize, SMEM_TOTAL_MMA);

    const int total_w = LAYERS * 6 * HH * HH;
    prep_w_kernel<<<(total_w + 255) / 256, 256>>>(Wq, Wk, Wv, Wi, Wf, Wo);

    dim3 ggrid(MM / 64, 6);
    dim3 sgrid(17, BB);
    const int nx4 = (MM * HH) / 4;

    // layer 0
    prep_x_kernel<<<nx4 / 256, 256>>>(x);
    mma_proj_kernel<<<ggrid, 256, SMEM_TOTAL_MMA>>>(0, bq, bk, bv, bi, bf, bo);
    scan_kernel<<<sgrid, 256>>>();                        // g_h (raw) + g_rden
    // layer 1 (normalization of layer-0 output fused into prep_x)
    prep_x_kernel<<<nx4 / 256, 256>>>(nullptr);
    mma_proj_kernel<<<ggrid, 256, SMEM_TOTAL_MMA>>>(1, bq, bk, bv, bi, bf, bo);
    scan_kernel<<<sgrid, 256>>>();                        // g_h (raw) + g_rden
    // final normalize into d_out
    normalize_kernel<<<(MM * HH) / 256, 256>>>(out);
}